// round 6
// baseline (speedup 1.0000x reference)
#include <cuda_runtime.h>
#include <cstdint>

#define H    512
#define G4   2048
#define SEQL 1024
#define EMB  300
#define NCTA 64
#define TPB  256

// Scratch: 8 MB xg precompute ([t][u][gate]) + 16 MB tagged gate ring.
__device__ float g_xg4[SEQL * G4];
__device__ __align__(16) unsigned long long g_gtag[SEQL * G4];

// ---------------------------------------------------------------------------
// Kernel 1: xg[t][u][g] = (b_ih[r]+b_hh[r]) + sum_e emb[tok[t]][e]*W_ih[r][e],
// r = g*512+u. 64x64 tile per block, 4x4 micro-tile per thread.
// ---------------------------------------------------------------------------
#define TK 16
__global__ __launch_bounds__(256) void xgemm_kernel(
    const int* __restrict__ tokens,
    const float* __restrict__ emb,
    const float* __restrict__ Wih,
    const float* __restrict__ bih,
    const float* __restrict__ bhh)
{
    __shared__ float Ws[64][TK + 1];
    __shared__ float Xs[64][TK + 1];
    __shared__ int   toks[64];

    const int row0 = blockIdx.x * 64;
    const int t0   = blockIdx.y * 64;
    const int tid  = threadIdx.x;
    const int tx = tid & 15, ty = tid >> 4;

    if (tid < 64) toks[tid] = tokens[t0 + tid];
    __syncthreads();

    float acc[4][4];
#pragma unroll
    for (int i = 0; i < 4; i++)
#pragma unroll
        for (int j = 0; j < 4; j++) acc[i][j] = 0.f;

    const int kk = tid & 15;
    const int ib = tid >> 4;

    for (int k0 = 0; k0 < EMB; k0 += TK) {
#pragma unroll
        for (int q = 0; q < 4; q++) {
            int i = ib + q * 16;
            int e = k0 + kk;
            long widx = (long)(row0 + i) * EMB + (e < EMB ? e : EMB - 1);
            Ws[i][kk] = Wih[widx];
            Xs[i][kk] = (e < EMB) ? emb[(long)toks[i] * EMB + e] : 0.f;
        }
        __syncthreads();
#pragma unroll
        for (int k = 0; k < TK; k++) {
            float a[4], x[4];
#pragma unroll
            for (int i = 0; i < 4; i++) a[i] = Ws[tx * 4 + i][k];
#pragma unroll
            for (int j = 0; j < 4; j++) x[j] = Xs[ty * 4 + j][k];
#pragma unroll
            for (int i = 0; i < 4; i++)
#pragma unroll
                for (int j = 0; j < 4; j++)
                    acc[i][j] += a[i] * x[j];
        }
        __syncthreads();
    }

#pragma unroll
    for (int i = 0; i < 4; i++) {
        int row = row0 + tx * 4 + i;
        float bias = bih[row] + bhh[row];
        int u = row & 511, g = row >> 9;
#pragma unroll
        for (int j = 0; j < 4; j++) {
            int t = t0 + ty * 4 + j;
            g_xg4[(long)t * G4 + u * 4 + g] = acc[i][j] + bias;   // [t][u][gate]
        }
    }
}

// ---------------------------------------------------------------------------
// packed fp32x2 FMA (sm_103a; only via PTX)
// ---------------------------------------------------------------------------
__device__ __forceinline__ void ffma2(unsigned long long& d,
                                      unsigned long long a, unsigned long long b)
{
    asm("fma.rn.f32x2 %0, %1, %2, %3;" : "=l"(d) : "l"(a), "l"(b), "l"(d));
}

__device__ __forceinline__ float fast_tanh(float x)
{
    float a = fabsf(x);
    float e = __expf(-2.f * a);
    float r = __fdividef(1.f - e, 1.f + e);
    return copysignf(r, x);
}
__device__ __forceinline__ float fast_sigmoid(float x)
{
    return __fdividef(1.f, 1.f + __expf(-x));
}

// ---------------------------------------------------------------------------
// Kernel 2: persistent LSTM, gate-broadcast variant.
// 64 CTAs x 256 threads. CTA b PRODUCES gate pre-activations for units
// 8b..8b+7 (warp w: gate w>>1, units +4(w&1)..+3) and publishes them tagged
// right after the xor-reduce (+xg bias) — nonlinearity is NOT on the
// publish path. Every CTA redundantly CONSUMES all 2048 gates and tracks
// (c, h, out) for all 512 units (2 per thread), computing the nonlinearity
// in parallel across 256 threads. Two barriers per step (mid + trailing
// lockstep; R2/R3 showed free-running warps regress ~2x).
// ---------------------------------------------------------------------------
// smem h layout: h[k] at f(k) = 18*(k>>4) + (k&15); lane reads 8 u64 at 18*lane.
__global__ __launch_bounds__(TPB, 1) void lstm_kernel(
    const int* __restrict__ tokens,
    const float* __restrict__ h0,
    const float* __restrict__ c0,
    const float* __restrict__ Whh,
    float* __restrict__ out)
{
    __shared__ __align__(16) float h_s[576];
    __shared__ int toks[SEQL];

    const int b    = blockIdx.x;
    const int tid  = threadIdx.x;
    const int w    = tid >> 5;
    const int lane = tid & 31;

    for (int i = tid; i < SEQL; i += TPB) toks[i] = tokens[i];

    // Producer weights: warp w -> gate g = w>>1, units ub..ub+3,
    // lane covers K in [16*lane, 16*lane+16) as 8 f32x2 pairs.
    const int g_gate = w >> 1;
    const int ub     = b * 8 + 4 * (w & 1);
    unsigned long long wp[4][8];
#pragma unroll
    for (int i = 0; i < 4; i++) {
        const float* wrow = Whh + (size_t)(g_gate * H + ub + i) * H + 16 * lane;
#pragma unroll
        for (int j = 0; j < 8; j++) {
            float2 f = *(const float2*)(wrow + 2 * j);
            unsigned long long v;
            asm("mov.b64 %0, {%1,%2};" : "=l"(v) : "f"(f.x), "f"(f.y));
            wp[i][j] = v;
        }
    }

    // Consumer state: units u0 = 2*tid, u1 = u0+1 (full redundant state).
    const int u0 = 2 * tid;
    float c_r0 = c0[u0],  c_r1 = c0[u0 + 1];
    float h_r0 = h0[u0],  h_r1 = h0[u0 + 1];
    float o_r0 = 0.f,     o_r1 = 0.f;

    unsigned long long* gtag = g_gtag;

    for (int t = 0; t < SEQL; t++) {
        // Producer-side xg prefetch: lane i<4 loads xg[t][ub+i][g_gate].
        float xgv = 0.f;
        if (lane < 4)
            xgv = g_xg4[(size_t)t * G4 + (ub + lane) * 4 + g_gate];

        if (t > 0) {
            // Consume gates(t-1): 8 tagged u64 (2 units x 4 gates), 4 loads in flight.
            const unsigned long long* ptr = gtag + (size_t)(t - 1) * G4 + 8 * tid;
            unsigned long long v0, v1, v2, v3, v4, v5, v6, v7;
            const unsigned tag = (unsigned)t;
            do {
                asm volatile("ld.volatile.global.v2.u64 {%0,%1},[%2];"
                             : "=l"(v0), "=l"(v1) : "l"(ptr));
                asm volatile("ld.volatile.global.v2.u64 {%0,%1},[%2];"
                             : "=l"(v2), "=l"(v3) : "l"(ptr + 2));
                asm volatile("ld.volatile.global.v2.u64 {%0,%1},[%2];"
                             : "=l"(v4), "=l"(v5) : "l"(ptr + 4));
                asm volatile("ld.volatile.global.v2.u64 {%0,%1},[%2];"
                             : "=l"(v6), "=l"(v7) : "l"(ptr + 6));
            } while ((unsigned)(v0 >> 32) != tag || (unsigned)(v1 >> 32) != tag ||
                     (unsigned)(v2 >> 32) != tag || (unsigned)(v3 >> 32) != tag ||
                     (unsigned)(v4 >> 32) != tag || (unsigned)(v5 >> 32) != tag ||
                     (unsigned)(v6 >> 32) != tag || (unsigned)(v7 >> 32) != tag);

            // Nonlinearity for 2 units, fully parallel across 256 threads.
            const bool upd = (toks[t - 1] != 1);        // PAD_IDX == 1
            {
                float si = fast_sigmoid(__uint_as_float((unsigned)v0));
                float sf = fast_sigmoid(__uint_as_float((unsigned)v1));
                float tg = fast_tanh   (__uint_as_float((unsigned)v2));
                float so = fast_sigmoid(__uint_as_float((unsigned)v3));
                float cn = sf * c_r0 + si * tg;
                float hn = so * fast_tanh(cn);
                if (upd) { c_r0 = cn; h_r0 = hn; o_r0 = hn; }
            }
            {
                float si = fast_sigmoid(__uint_as_float((unsigned)v4));
                float sf = fast_sigmoid(__uint_as_float((unsigned)v5));
                float tg = fast_tanh   (__uint_as_float((unsigned)v6));
                float so = fast_sigmoid(__uint_as_float((unsigned)v7));
                float cn = sf * c_r1 + si * tg;
                float hn = so * fast_tanh(cn);
                if (upd) { c_r1 = cn; h_r1 = hn; o_r1 = hn; }
            }
        }
        // h_{t-1} into padded smem (u0 even -> consecutive padded slots).
        {
            float2 hv; hv.x = h_r0; hv.y = h_r1;
            *(float2*)&h_s[18 * (u0 >> 4) + (u0 & 15)] = hv;
        }
        __syncthreads();

        // Producer dot: 4 gate rows x 16 K per thread, f32x2, weights in regs.
        unsigned long long a0 = 0ull, a1 = 0ull, a2 = 0ull, a3 = 0ull;
        const unsigned long long* hb =
            (const unsigned long long*)&h_s[18 * lane];
#pragma unroll
        for (int j = 0; j < 8; j++) {
            unsigned long long hv = hb[j];
            ffma2(a0, wp[0][j], hv);
            ffma2(a1, wp[1][j], hv);
            ffma2(a2, wp[2][j], hv);
            ffma2(a3, wp[3][j], hv);
        }
        float acc0, acc1, acc2, acc3;
        {
            float lo, hi;
            asm("mov.b64 {%0,%1}, %2;" : "=f"(lo), "=f"(hi) : "l"(a0)); acc0 = lo + hi;
            asm("mov.b64 {%0,%1}, %2;" : "=f"(lo), "=f"(hi) : "l"(a1)); acc1 = lo + hi;
            asm("mov.b64 {%0,%1}, %2;" : "=f"(lo), "=f"(hi) : "l"(a2)); acc2 = lo + hi;
            asm("mov.b64 {%0,%1}, %2;" : "=f"(lo), "=f"(hi) : "l"(a3)); acc3 = lo + hi;
        }
#pragma unroll
        for (int off = 16; off > 0; off >>= 1) {
            acc0 += __shfl_xor_sync(0xffffffffu, acc0, off);
            acc1 += __shfl_xor_sync(0xffffffffu, acc1, off);
            acc2 += __shfl_xor_sync(0xffffffffu, acc2, off);
            acc3 += __shfl_xor_sync(0xffffffffu, acc3, off);
        }
        // All lanes hold all 4 sums; lanes 0..3 publish row ub+lane (+xg).
        if (lane < 4) {
            float s = (lane == 0) ? acc0 : (lane == 1) ? acc1
                     : (lane == 2) ? acc2 : acc3;
            s += xgv;
            unsigned long long v =
                ((unsigned long long)(unsigned)(t + 1) << 32) |
                (unsigned long long)__float_as_uint(s);
            gtag[(size_t)t * G4 + (ub + lane) * 4 + g_gate] = v;
        }
        __syncthreads();   // lockstep (load-bearing per R2/R3)
    }

    // Final consume of gates(SEQL-1): CTA 0 finishes the state and writes out.
    if (b == 0) {
        const unsigned long long* ptr =
            gtag + (size_t)(SEQL - 1) * G4 + 8 * tid;
        unsigned long long v0, v1, v2, v3, v4, v5, v6, v7;
        const unsigned tag = (unsigned)SEQL;
        do {
            asm volatile("ld.volatile.global.v2.u64 {%0,%1},[%2];"
                         : "=l"(v0), "=l"(v1) : "l"(ptr));
            asm volatile("ld.volatile.global.v2.u64 {%0,%1},[%2];"
                         : "=l"(v2), "=l"(v3) : "l"(ptr + 2));
            asm volatile("ld.volatile.global.v2.u64 {%0,%1},[%2];"
                         : "=l"(v4), "=l"(v5) : "l"(ptr + 4));
            asm volatile("ld.volatile.global.v2.u64 {%0,%1},[%2];"
                         : "=l"(v6), "=l"(v7) : "l"(ptr + 6));
        } while ((unsigned)(v0 >> 32) != tag || (unsigned)(v1 >> 32) != tag ||
                 (unsigned)(v2 >> 32) != tag || (unsigned)(v3 >> 32) != tag ||
                 (unsigned)(v4 >> 32) != tag || (unsigned)(v5 >> 32) != tag ||
                 (unsigned)(v6 >> 32) != tag || (unsigned)(v7 >> 32) != tag);

        const bool upd = (toks[SEQL - 1] != 1);
        {
            float si = fast_sigmoid(__uint_as_float((unsigned)v0));
            float sf = fast_sigmoid(__uint_as_float((unsigned)v1));
            float tg = fast_tanh   (__uint_as_float((unsigned)v2));
            float so = fast_sigmoid(__uint_as_float((unsigned)v3));
            float cn = sf * c_r0 + si * tg;
            float hn = so * fast_tanh(cn);
            if (upd) { c_r0 = cn; h_r0 = hn; o_r0 = hn; }
        }
        {
            float si = fast_sigmoid(__uint_as_float((unsigned)v4));
            float sf = fast_sigmoid(__uint_as_float((unsigned)v5));
            float tg = fast_tanh   (__uint_as_float((unsigned)v6));
            float so = fast_sigmoid(__uint_as_float((unsigned)v7));
            float cn = sf * c_r1 + si * tg;
            float hn = so * fast_tanh(cn);
            if (upd) { c_r1 = cn; h_r1 = hn; o_r1 = hn; }
        }
        out[u0]              = o_r0;  out[u0 + 1]          = o_r1;  // out
        out[H + u0]          = h_r0;  out[H + u0 + 1]      = h_r1;  // h
        out[2 * H + u0]      = c_r0;  out[2 * H + u0 + 1]  = c_r1;  // c
    }
}

extern "C" void kernel_launch(void* const* d_in, const int* in_sizes, int n_in,
                              void* d_out, int out_size)
{
    const int*   tokens = (const int*)  d_in[0];
    const float* h0     = (const float*)d_in[1];
    const float* c0     = (const float*)d_in[2];
    const float* emb    = (const float*)d_in[3];
    const float* Wih    = (const float*)d_in[4];
    const float* Whh    = (const float*)d_in[5];
    const float* bih    = (const float*)d_in[6];
    const float* bhh    = (const float*)d_in[7];
    float* out = (float*)d_out;

    // Reset the gate-tag ring every launch (deterministic across replays).
    void* gtag_ptr = nullptr;
    cudaGetSymbolAddress(&gtag_ptr, g_gtag);
    cudaMemsetAsync(gtag_ptr, 0, sizeof(unsigned long long) * SEQL * G4);

    dim3 g1(G4 / 64, SEQL / 64);
    xgemm_kernel<<<g1, 256>>>(tokens, emb, Wih, bih, bhh);
    lstm_kernel<<<NCTA, TPB>>>(tokens, h0, c0, Whh, out);
}

// round 8
// speedup vs baseline: 1.9201x; 1.9201x over previous
#include <cuda_runtime.h>
#include <cstdint>

#define H    512
#define G4   2048
#define SEQL 1024
#define EMB  300
#define NCTA 64
#define TPB  256

// Scratch: 8 MB gate-precompute (transposed [t][u][gate]) + 4 MB tagged-h ring.
__device__ float g_xg4[SEQL * G4];
__device__ __align__(16) unsigned long long g_htag[SEQL * H];

// ---------------------------------------------------------------------------
// Kernel 1: xg[t][u][g] = (b_ih[r]+b_hh[r]) + sum_e emb[tok[t]][e]*W_ih[r][e],
// r = g*512+u. 64x64 tile per block, 4x4 micro-tile per thread.
// ---------------------------------------------------------------------------
#define TK 16
__global__ __launch_bounds__(256) void xgemm_kernel(
    const int* __restrict__ tokens,
    const float* __restrict__ emb,
    const float* __restrict__ Wih,
    const float* __restrict__ bih,
    const float* __restrict__ bhh)
{
    __shared__ float Ws[64][TK + 1];
    __shared__ float Xs[64][TK + 1];
    __shared__ int   toks[64];

    const int row0 = blockIdx.x * 64;
    const int t0   = blockIdx.y * 64;
    const int tid  = threadIdx.x;
    const int tx = tid & 15, ty = tid >> 4;

    if (tid < 64) toks[tid] = tokens[t0 + tid];
    __syncthreads();

    float acc[4][4];
#pragma unroll
    for (int i = 0; i < 4; i++)
#pragma unroll
        for (int j = 0; j < 4; j++) acc[i][j] = 0.f;

    const int kk = tid & 15;
    const int ib = tid >> 4;

    for (int k0 = 0; k0 < EMB; k0 += TK) {
#pragma unroll
        for (int q = 0; q < 4; q++) {
            int i = ib + q * 16;
            int e = k0 + kk;
            long widx = (long)(row0 + i) * EMB + (e < EMB ? e : EMB - 1);
            Ws[i][kk] = Wih[widx];
            Xs[i][kk] = (e < EMB) ? emb[(long)toks[i] * EMB + e] : 0.f;
        }
        __syncthreads();
#pragma unroll
        for (int k = 0; k < TK; k++) {
            float a[4], x[4];
#pragma unroll
            for (int i = 0; i < 4; i++) a[i] = Ws[tx * 4 + i][k];
#pragma unroll
            for (int j = 0; j < 4; j++) x[j] = Xs[ty * 4 + j][k];
#pragma unroll
            for (int i = 0; i < 4; i++)
#pragma unroll
                for (int j = 0; j < 4; j++)
                    acc[i][j] += a[i] * x[j];
        }
        __syncthreads();
    }

#pragma unroll
    for (int i = 0; i < 4; i++) {
        int row = row0 + tx * 4 + i;
        float bias = bih[row] + bhh[row];
        int u = row & 511, g = row >> 9;
#pragma unroll
        for (int j = 0; j < 4; j++) {
            int t = t0 + ty * 4 + j;
            g_xg4[(long)t * G4 + u * 4 + g] = acc[i][j] + bias;   // [t][u][gate]
        }
    }
}

// ---------------------------------------------------------------------------
// packed fp32x2 ops (sm_103a; only via PTX)
// ---------------------------------------------------------------------------
__device__ __forceinline__ void ffma2(unsigned long long& d,
                                      unsigned long long a, unsigned long long b)
{
    asm("fma.rn.f32x2 %0, %1, %2, %3;" : "=l"(d) : "l"(a), "l"(b), "l"(d));
}
__device__ __forceinline__ void fadd2(unsigned long long& d,
                                      unsigned long long a, unsigned long long b)
{
    asm("add.rn.f32x2 %0, %1, %2;" : "=l"(d) : "l"(a), "l"(b));
}

__device__ __forceinline__ float fast_tanh(float x)
{
    float a = fabsf(x);
    float e = __expf(-2.f * a);
    float r = __fdividef(1.f - e, 1.f + e);
    return copysignf(r, x);
}
__device__ __forceinline__ float fast_sigmoid(float x)
{
    return __fdividef(1.f, 1.f + __expf(-x));
}

// ---------------------------------------------------------------------------
// Kernel 2: persistent LSTM recurrence.
// 64 CTAs x 256 threads, lockstep (trailing barrier is load-bearing: R2/R3
// showed free-running warps starve the publish-critical chain ~2x).
// Warp w owns hidden unit u = 8b + w. 8-lane quarter g = lane>>3 computes
// gate row g*512+u (64 weights as 32 f32x2 in regs). Nonlinearity + tagged
// publish run in lane 0 of ALL warps in parallel — no gates smem, no mid
// barrier. Poll is paced (~96-cyc clock backoff after a miss) to keep LTS
// queues shallow (R4/R5 ncu: unpaced polling pins LTS at the chip cap).
//
// smem h layout: h[k] at f(k) = 18*(k>>4) + (k&15). Lane-slot q, pair j
// reads k = 2q + 16j  ->  float offset 18j + 2q  ->  u64 base &h_s[2q],
// stride 9 per j. (R6 had this transposed: base 18q stride 2 — wrong data.)
// ---------------------------------------------------------------------------
__global__ __launch_bounds__(TPB, 1) void lstm_kernel(
    const int* __restrict__ tokens,
    const float* __restrict__ h0,
    const float* __restrict__ c0,
    const float* __restrict__ Whh,
    float* __restrict__ out)
{
    __shared__ __align__(16) float h_s[576];
    __shared__ int toks[SEQL];

    const int b    = blockIdx.x;
    const int tid  = threadIdx.x;
    const int w    = tid >> 5;
    const int lane = tid & 31;
    const int g    = lane >> 3;          // gate handled by this lane group
    const int q    = lane & 7;           // K-slot within gate group
    const int u    = b * 8 + w;          // hidden unit owned by this warp

    for (int i = tid; i < SEQL; i += TPB) toks[i] = tokens[i];

    // Weights for gate row g*H+u: pairs k = 2*q + 16*j, j = 0..31.
    unsigned long long wp[32];
    {
        const float* wrow = Whh + (size_t)(g * H + u) * H;
#pragma unroll
        for (int j = 0; j < 32; j++) {
            float2 f = *(const float2*)(wrow + 2 * q + 16 * j);
            unsigned long long v;
            asm("mov.b64 %0, {%1,%2};" : "=l"(v) : "f"(f.x), "f"(f.y));
            wp[j] = v;
        }
    }

    float c_reg = 0.f, h_last = 0.f, out_reg = 0.f;
    if (lane == 0) { c_reg = c0[u]; h_last = h0[u]; }

    unsigned long long* htag = g_htag;

    for (int t = 0; t < SEQL; t++) {
        // lane 0 prefetches this unit's 4 gate biases (1 LDG.128),
        // latency hidden behind the poll below.
        float4 xgv = make_float4(0.f, 0.f, 0.f, 0.f);
        if (lane == 0)
            xgv = *(const float4*)(g_xg4 + (size_t)t * G4 + u * 4);

        // Acquire h_{t-1} into padded smem (thread handles k0 = 2*tid, +1).
        {
            const int k0 = 2 * tid;
            float* dst = &h_s[18 * (k0 >> 4) + (k0 & 15)];
            if (t == 0) {
                *(float2*)dst = *(const float2*)(h0 + k0);
            } else {
                const unsigned long long* ptr =
                    htag + (size_t)(t - 1) * H + k0;
                unsigned long long v0, v1;
                const unsigned tag = (unsigned)t;
                for (;;) {
                    asm volatile("ld.volatile.global.v2.u64 {%0,%1},[%2];"
                                 : "=l"(v0), "=l"(v1) : "l"(ptr));
                    if ((unsigned)(v0 >> 32) == tag &&
                        (unsigned)(v1 >> 32) == tag) break;
                    unsigned s = (unsigned)clock();          // paced re-poll
                    while ((unsigned)clock() - s < 96u) { }
                }
                float2 hv;
                hv.x = __uint_as_float((unsigned)v0);
                hv.y = __uint_as_float((unsigned)v1);
                *(float2*)dst = hv;
            }
        }
        __syncthreads();

        // Dot: 64 weights x h via 32 f32x2, 4 interleaved accumulators.
        // Pair j lives at u64 index 9*j from base &h_s[2*q].
        unsigned long long a0 = 0ull, a1 = 0ull, a2 = 0ull, a3 = 0ull;
        const unsigned long long* hb =
            (const unsigned long long*)&h_s[2 * q];
#pragma unroll
        for (int j = 0; j < 32; j += 4) {
            ffma2(a0, wp[j + 0], hb[9 * (j + 0)]);
            ffma2(a1, wp[j + 1], hb[9 * (j + 1)]);
            ffma2(a2, wp[j + 2], hb[9 * (j + 2)]);
            ffma2(a3, wp[j + 3], hb[9 * (j + 3)]);
        }
        fadd2(a0, a0, a1);
        fadd2(a2, a2, a3);
        fadd2(a0, a0, a2);
        float lo, hi;
        asm("mov.b64 {%0,%1}, %2;" : "=f"(lo), "=f"(hi) : "l"(a0));
        float acc = lo + hi;

        // Reduce across the 8-lane gate group.
        acc += __shfl_xor_sync(0xffffffffu, acc, 4);
        acc += __shfl_xor_sync(0xffffffffu, acc, 2);
        acc += __shfl_xor_sync(0xffffffffu, acc, 1);

        // Gather the four gate sums (lanes 0, 8, 16, 24) to all lanes.
        float s_i = __shfl_sync(0xffffffffu, acc, 0);
        float s_f = __shfl_sync(0xffffffffu, acc, 8);
        float s_g = __shfl_sync(0xffffffffu, acc, 16);
        float s_o = __shfl_sync(0xffffffffu, acc, 24);

        if (lane == 0) {
            float si = fast_sigmoid(s_i + xgv.x);
            float sf = fast_sigmoid(s_f + xgv.y);
            float tg = fast_tanh   (s_g + xgv.z);
            float so = fast_sigmoid(s_o + xgv.w);
            float c_new = sf * c_reg + si * tg;
            float h_new = so * fast_tanh(c_new);
            if (toks[t] != 1) {                 // PAD_IDX == 1
                c_reg  = c_new;
                h_last = h_new;
                out_reg = h_new;
            }
            unsigned long long v =
                ((unsigned long long)(unsigned)(t + 1) << 32) |
                (unsigned long long)__float_as_uint(h_last);
            htag[(size_t)t * H + u] = v;
        }
        __syncthreads();   // lockstep: load-bearing (R2/R3 post-mortems)
    }

    if (lane == 0) {
        out[u]         = out_reg;  // out
        out[H + u]     = h_last;   // h
        out[2 * H + u] = c_reg;    // c
    }
}

extern "C" void kernel_launch(void* const* d_in, const int* in_sizes, int n_in,
                              void* d_out, int out_size)
{
    const int*   tokens = (const int*)  d_in[0];
    const float* h0     = (const float*)d_in[1];
    const float* c0     = (const float*)d_in[2];
    const float* emb    = (const float*)d_in[3];
    const float* Wih    = (const float*)d_in[4];
    const float* Whh    = (const float*)d_in[5];
    const float* bih    = (const float*)d_in[6];
    const float* bhh    = (const float*)d_in[7];
    float* out = (float*)d_out;

    // Reset the tag buffer every launch (deterministic across graph replays).
    void* htag_ptr = nullptr;
    cudaGetSymbolAddress(&htag_ptr, g_htag);
    cudaMemsetAsync(htag_ptr, 0, sizeof(unsigned long long) * SEQL * H);

    dim3 g1(G4 / 64, SEQL / 64);
    xgemm_kernel<<<g1, 256>>>(tokens, emb, Wih, bih, bhh);
    lstm_kernel<<<NCTA, TPB>>>(tokens, h0, c0, Whh, out);
}